// round 5
// baseline (speedup 1.0000x reference)
#include <cuda_runtime.h>

// Problem constants (fixed shapes per reference):
//   x0: [8,256,256,64] f32  -> 33,554,432 floats
//   x1: [8,128,128,64] f32  ->  8,388,608 floats
// Output = concat(out0 [8,256,256,64], repl [8,128,128,64], out3 [8,256,256,64])
//        = 75,497,472 floats.
//
// float4-vectorized: N4 = 8*128*128*16 = 2,097,152 threads.
// Pure one-touch stream: evict-first cache hints on both loads and stores,
// and 6 blocks/SM to deepen the outstanding-load queue.

#define N4        2097152
#define OUT0_F4   0          // float4 offset of first output
#define REPL_F4   8388608    // 33,554,432 / 4
#define OUT3_F4   10485760   // + 8,388,608 / 4

// Per-channel "learned-sort unpool" math. v0..v3 = block values (row-major
// within the 2x2 block); p = pooled value.
__device__ __forceinline__ void lane(
    float v0, float v1, float v2, float v3, float p,
    float& o0, float& o1, float& o2, float& o3,
    float& rep,
    float& q0, float& q1, float& q2, float& q3)
{
    // Value-only descending sort (5-comparator network).
    float a0 = fmaxf(v0, v1), a1 = fminf(v0, v1);
    float a2 = fmaxf(v2, v3), a3 = fminf(v2, v3);
    float s0 = fmaxf(a0, a2), m0 = fminf(a0, a2);
    float s3t = fminf(a1, a3), m1 = fmaxf(a1, a3);
    float s1 = fmaxf(m1, m0), s2 = fminf(m1, m0);
    // sorted descending: s0 >= s1 >= s2 >= s3t

    // Optimal-average scan: avg_j = (sum of top j+1 + p) / (j+2); first max.
    float cs   = s0 + p;
    float best = cs / 2.0f;
    int   k    = 0;
    cs += s1; { float t = cs / 3.0f; if (t > best) { best = t; k = 1; } }
    cs += s2; { float t = cs / 4.0f; if (t > best) { best = t; k = 2; } }
    cs += s3t;{ float t = cs / 5.0f; if (t > best) { best = t; k = 3; } }
    rep = best;

    float frac = (float)(k + 1) / (float)(k + 2);

    // Stable descending rank of each original position:
    // rank_l = #{m : v_m > v_l} + #{m < l : v_m == v_l}
    int r0 = (int)(v1 > v0)  + (int)(v2 > v0)  + (int)(v3 > v0);
    int r1 = (int)(v0 >= v1) + (int)(v2 > v1)  + (int)(v3 > v1);
    int r2 = (int)(v0 >= v2) + (int)(v1 >= v2) + (int)(v3 > v2);
    int r3 = (int)(v0 >= v3) + (int)(v1 >= v3) + (int)(v2 >= v3);

    bool m0b = r0 <= k, m1b = r1 <= k, m2b = r2 <= k, m3b = r3 <= k;
    o0 = m0b ? best : v0;  q0 = m0b ? frac : 1.0f;
    o1 = m1b ? best : v1;  q1 = m1b ? frac : 1.0f;
    o2 = m2b ? best : v2;  q2 = m2b ? frac : 1.0f;
    o3 = m3b ? best : v3;  q3 = m3b ? frac : 1.0f;
}

__global__ void __launch_bounds__(256, 6)
unpool_ls_kernel(const float4* __restrict__ x0,
                 const float4* __restrict__ x1,
                 float4* __restrict__ out)
{
    int idx = blockIdx.x * 256 + threadIdx.x;   // grid covers exactly N4

    // idx decomposition: [b:3][h:7][w:7][c4:4]
    int c4 = idx & 15;
    int t  = idx >> 4;
    int w  = t & 127;
    t >>= 7;
    int h  = t & 127;
    int b  = t >> 7;

    // x0 float4 index of block corner (2h, 2w):
    // ((b*256 + 2h)*256 + 2w)*16 + c4 ; row stride (W*C/4) = 4096 float4.
    int base = ((b * 256 + 2 * h) * 256 + 2 * w) * 16 + c4;

    // Evict-first loads: one-touch data, keep L2 clean.
    float4 A  = __ldcs(x0 + base);          // (2h,   2w)
    float4 Bv = __ldcs(x0 + base + 16);     // (2h,   2w+1)
    float4 Cv = __ldcs(x0 + base + 4096);   // (2h+1, 2w)
    float4 D  = __ldcs(x0 + base + 4112);   // (2h+1, 2w+1)
    float4 P  = __ldcs(x1 + idx);           // pooled

    float4 OA, OB, OC, OD, R, TA, TB, TC, TD;

    lane(A.x, Bv.x, Cv.x, D.x, P.x, OA.x, OB.x, OC.x, OD.x, R.x, TA.x, TB.x, TC.x, TD.x);
    lane(A.y, Bv.y, Cv.y, D.y, P.y, OA.y, OB.y, OC.y, OD.y, R.y, TA.y, TB.y, TC.y, TD.y);
    lane(A.z, Bv.z, Cv.z, D.z, P.z, OA.z, OB.z, OC.z, OD.z, R.z, TA.z, TB.z, TC.z, TD.z);
    lane(A.w, Bv.w, Cv.w, D.w, P.w, OA.w, OB.w, OC.w, OD.w, R.w, TA.w, TB.w, TC.w, TD.w);

    // out0 (same layout as x0) — streaming stores
    __stcs(out + OUT0_F4 + base,        OA);
    __stcs(out + OUT0_F4 + base + 16,   OB);
    __stcs(out + OUT0_F4 + base + 4096, OC);
    __stcs(out + OUT0_F4 + base + 4112, OD);

    // repl (pooled layout)
    __stcs(out + REPL_F4 + idx, R);

    // out3 (same layout as x0)
    int b3 = OUT3_F4 + base;
    __stcs(out + b3,        TA);
    __stcs(out + b3 + 16,   TB);
    __stcs(out + b3 + 4096, TC);
    __stcs(out + b3 + 4112, TD);
}

extern "C" void kernel_launch(void* const* d_in, const int* in_sizes, int n_in,
                              void* d_out, int out_size)
{
    (void)in_sizes; (void)n_in; (void)out_size;
    const float4* x0 = (const float4*)d_in[0];
    const float4* x1 = (const float4*)d_in[1];
    float4* out = (float4*)d_out;

    unpool_ls_kernel<<<N4 / 256, 256>>>(x0, x1, out);
}

// round 6
// speedup vs baseline: 1.0043x; 1.0043x over previous
#include <cuda_runtime.h>

// Shapes: x0 [8,256,256,64] f32, x1 [8,128,128,64] f32.
// Output = concat(out0 [8,256,256,64], repl [8,128,128,64], out3 [8,256,256,64]).
//
// Each thread handles TWO adjacent pooled blocks (a w-pair) for one c4 group:
// 10 independent float4 loads front-batched (deep MLP), 18 stores.
// No cache hints, no launch bounds (R2 showed both regress on this stream).

#define NTHREADS  1048576     // 8*128*64*16
#define BLOCK     128
#define REPL_F4   8388608     // 33,554,432 / 4
#define OUT3_F4   10485760    // + 8,388,608 / 4

__device__ __forceinline__ void lane(
    float v0, float v1, float v2, float v3, float p,
    float& o0, float& o1, float& o2, float& o3,
    float& rep,
    float& q0, float& q1, float& q2, float& q3)
{
    // Value-only descending sort (5-comparator network).
    float a0 = fmaxf(v0, v1), a1 = fminf(v0, v1);
    float a2 = fmaxf(v2, v3), a3 = fminf(v2, v3);
    float s0 = fmaxf(a0, a2), m0 = fminf(a0, a2);
    float s3t = fminf(a1, a3), m1 = fmaxf(a1, a3);
    float s1 = fmaxf(m1, m0), s2 = fminf(m1, m0);

    // Optimal-average scan: avg_j = (cumsum_j + p)/(j+2); first max wins.
    float cs   = s0 + p;
    float best = cs / 2.0f;
    int   k    = 0;
    cs += s1; { float t = cs / 3.0f; if (t > best) { best = t; k = 1; } }
    cs += s2; { float t = cs / 4.0f; if (t > best) { best = t; k = 2; } }
    cs += s3t;{ float t = cs / 5.0f; if (t > best) { best = t; k = 3; } }
    rep = best;

    float frac = (float)(k + 1) / (float)(k + 2);

    // Stable descending rank: rank_l = #{m: v_m > v_l} + #{m<l: v_m == v_l}
    int r0 = (int)(v1 > v0)  + (int)(v2 > v0)  + (int)(v3 > v0);
    int r1 = (int)(v0 >= v1) + (int)(v2 > v1)  + (int)(v3 > v1);
    int r2 = (int)(v0 >= v2) + (int)(v1 >= v2) + (int)(v3 > v2);
    int r3 = (int)(v0 >= v3) + (int)(v1 >= v3) + (int)(v2 >= v3);

    bool m0b = r0 <= k, m1b = r1 <= k, m2b = r2 <= k, m3b = r3 <= k;
    o0 = m0b ? best : v0;  q0 = m0b ? frac : 1.0f;
    o1 = m1b ? best : v1;  q1 = m1b ? frac : 1.0f;
    o2 = m2b ? best : v2;  q2 = m2b ? frac : 1.0f;
    o3 = m3b ? best : v3;  q3 = m3b ? frac : 1.0f;
}

// Process one 2x2 block (4 channels via float4 SIMD-in-register).
__device__ __forceinline__ void do_block(
    float4 A, float4 Bv, float4 Cv, float4 D, float4 P,
    float4& OA, float4& OB, float4& OC, float4& OD,
    float4& R, float4& TA, float4& TB, float4& TC, float4& TD)
{
    lane(A.x, Bv.x, Cv.x, D.x, P.x, OA.x, OB.x, OC.x, OD.x, R.x, TA.x, TB.x, TC.x, TD.x);
    lane(A.y, Bv.y, Cv.y, D.y, P.y, OA.y, OB.y, OC.y, OD.y, R.y, TA.y, TB.y, TC.y, TD.y);
    lane(A.z, Bv.z, Cv.z, D.z, P.z, OA.z, OB.z, OC.z, OD.z, R.z, TA.z, TB.z, TC.z, TD.z);
    lane(A.w, Bv.w, Cv.w, D.w, P.w, OA.w, OB.w, OC.w, OD.w, R.w, TA.w, TB.w, TC.w, TD.w);
}

__global__ void unpool_ls_kernel(const float4* __restrict__ x0,
                                 const float4* __restrict__ x1,
                                 float4* __restrict__ out)
{
    int idx = blockIdx.x * BLOCK + threadIdx.x;   // covers exactly NTHREADS

    // idx decomposition: [b:3][h:7][wp:6][c4:4]  (wp = pooled-w pair)
    int c4 = idx & 15;
    int t  = idx >> 4;
    int wp = t & 63;
    t >>= 6;
    int h  = t & 127;
    int b  = t >> 7;

    // x0 float4 base at (2h, 4wp): row stride = 4096 float4.
    int base  = (b * 256 + 2 * h) * 4096 + wp * 64 + c4;
    // x1 float4 index at (h, 2wp):
    int pidx  = (b * 128 + h) * 2048 + wp * 32 + c4;

    // Front-batched independent loads (10 x LDG.128).
    float4 A0 = x0[base];            // blk0 (2h,   4wp)
    float4 B0 = x0[base + 16];       // blk0 (2h,   4wp+1)
    float4 A1 = x0[base + 32];       // blk1 (2h,   4wp+2)
    float4 B1 = x0[base + 48];       // blk1 (2h,   4wp+3)
    float4 C0 = x0[base + 4096];     // blk0 (2h+1, 4wp)
    float4 D0 = x0[base + 4112];     // blk0 (2h+1, 4wp+1)
    float4 C1 = x0[base + 4128];     // blk1 (2h+1, 4wp+2)
    float4 D1 = x0[base + 4144];     // blk1 (2h+1, 4wp+3)
    float4 P0 = x1[pidx];            // pooled (h, 2wp)
    float4 P1 = x1[pidx + 16];       // pooled (h, 2wp+1)

    float4 OA, OB, OC, OD, R, TA, TB, TC, TD;

    // ---- block 0 ----
    do_block(A0, B0, C0, D0, P0, OA, OB, OC, OD, R, TA, TB, TC, TD);
    out[base]            = OA;
    out[base + 16]       = OB;
    out[base + 4096]     = OC;
    out[base + 4112]     = OD;
    out[REPL_F4 + pidx]  = R;
    out[OUT3_F4 + base]        = TA;
    out[OUT3_F4 + base + 16]   = TB;
    out[OUT3_F4 + base + 4096] = TC;
    out[OUT3_F4 + base + 4112] = TD;

    // ---- block 1 ----
    do_block(A1, B1, C1, D1, P1, OA, OB, OC, OD, R, TA, TB, TC, TD);
    out[base + 32]       = OA;
    out[base + 48]       = OB;
    out[base + 4128]     = OC;
    out[base + 4144]     = OD;
    out[REPL_F4 + pidx + 16] = R;
    out[OUT3_F4 + base + 32]   = TA;
    out[OUT3_F4 + base + 48]   = TB;
    out[OUT3_F4 + base + 4128] = TC;
    out[OUT3_F4 + base + 4144] = TD;
}

extern "C" void kernel_launch(void* const* d_in, const int* in_sizes, int n_in,
                              void* d_out, int out_size)
{
    (void)in_sizes; (void)n_in; (void)out_size;
    const float4* x0 = (const float4*)d_in[0];
    const float4* x1 = (const float4*)d_in[1];
    float4* out = (float4*)d_out;

    unpool_ls_kernel<<<NTHREADS / BLOCK, BLOCK>>>(x0, x1, out);
}

// round 7
// speedup vs baseline: 1.0078x; 1.0035x over previous
#include <cuda_runtime.h>

// Shapes: x0 [8,256,256,64] f32, x1 [8,128,128,64] f32.
// Output = concat(out0 [8,256,256,64], repl [8,128,128,64], out3 [8,256,256,64]).
//
// One thread = one 2x2 block x 8 channels, moved with Blackwell 256-bit
// ld/st.global.v8.f32 (sm_100+). 5 x 32B loads, 9 x 32B stores per thread.
// All offsets are 32B-aligned (c8*8 floats). Warp accesses: 8 lanes cover a
// 256B-contiguous channel line per pixel -> fully dense sectors.

#define NTHREADS  1048576     // 8*128*128*8
#define BLOCK     128
#define REPL_F    33554432    // float offset of repl region
#define OUT3_F    41943040    // float offset of out3 region

struct f8 { float v0,v1,v2,v3,v4,v5,v6,v7; };

__device__ __forceinline__ f8 ldg256(const float* p) {
    f8 r;
    asm("ld.global.v8.f32 {%0,%1,%2,%3,%4,%5,%6,%7}, [%8];"
        : "=f"(r.v0), "=f"(r.v1), "=f"(r.v2), "=f"(r.v3),
          "=f"(r.v4), "=f"(r.v5), "=f"(r.v6), "=f"(r.v7)
        : "l"(p));
    return r;
}

__device__ __forceinline__ void stg256(float* p, const f8& r) {
    asm volatile("st.global.v8.f32 [%0], {%1,%2,%3,%4,%5,%6,%7,%8};"
        :: "l"(p),
           "f"(r.v0), "f"(r.v1), "f"(r.v2), "f"(r.v3),
           "f"(r.v4), "f"(r.v5), "f"(r.v6), "f"(r.v7)
        : "memory");
}

// Per-channel "learned-sort unpool" math.
__device__ __forceinline__ void lane(
    float v0, float v1, float v2, float v3, float p,
    float& o0, float& o1, float& o2, float& o3,
    float& rep,
    float& q0, float& q1, float& q2, float& q3)
{
    // Value-only descending sort (5-comparator network).
    float a0 = fmaxf(v0, v1), a1 = fminf(v0, v1);
    float a2 = fmaxf(v2, v3), a3 = fminf(v2, v3);
    float s0 = fmaxf(a0, a2), m0 = fminf(a0, a2);
    float s3t = fminf(a1, a3), m1 = fmaxf(a1, a3);
    float s1 = fmaxf(m1, m0), s2 = fminf(m1, m0);

    // Optimal-average scan: avg_j = (cumsum_j + p)/(j+2); first max wins.
    float cs   = s0 + p;
    float best = cs / 2.0f;
    int   k    = 0;
    cs += s1; { float t = cs / 3.0f; if (t > best) { best = t; k = 1; } }
    cs += s2; { float t = cs / 4.0f; if (t > best) { best = t; k = 2; } }
    cs += s3t;{ float t = cs / 5.0f; if (t > best) { best = t; k = 3; } }
    rep = best;

    float frac = (float)(k + 1) / (float)(k + 2);

    // Stable descending rank: rank_l = #{m: v_m > v_l} + #{m<l: v_m == v_l}
    int r0 = (int)(v1 > v0)  + (int)(v2 > v0)  + (int)(v3 > v0);
    int r1 = (int)(v0 >= v1) + (int)(v2 > v1)  + (int)(v3 > v1);
    int r2 = (int)(v0 >= v2) + (int)(v1 >= v2) + (int)(v3 > v2);
    int r3 = (int)(v0 >= v3) + (int)(v1 >= v3) + (int)(v2 >= v3);

    bool m0b = r0 <= k, m1b = r1 <= k, m2b = r2 <= k, m3b = r3 <= k;
    o0 = m0b ? best : v0;  q0 = m0b ? frac : 1.0f;
    o1 = m1b ? best : v1;  q1 = m1b ? frac : 1.0f;
    o2 = m2b ? best : v2;  q2 = m2b ? frac : 1.0f;
    o3 = m3b ? best : v3;  q3 = m3b ? frac : 1.0f;
}

#define LANE(F) lane(A.F, Bv.F, Cv.F, D.F, P.F, \
                     OA.F, OB.F, OC.F, OD.F, R.F, TA.F, TB.F, TC.F, TD.F)

__global__ void unpool_ls_kernel(const float* __restrict__ x0,
                                 const float* __restrict__ x1,
                                 float* __restrict__ out)
{
    int idx = blockIdx.x * BLOCK + threadIdx.x;   // covers exactly NTHREADS

    // idx decomposition: [b:3][h:7][w:7][c8:3]
    int c8 = idx & 7;
    int t  = idx >> 3;
    int w  = t & 127;
    t >>= 7;
    int h  = t & 127;
    int b  = t >> 7;

    // x0 float offset of (2h, 2w, c8*8); row stride = 256*64 = 16384 floats.
    int base = ((b * 256 + 2 * h) * 256 + 2 * w) * 64 + c8 * 8;
    // x1 float offset of (h, w, c8*8).
    int pidx = idx * 8;

    // Front-batched independent 256-bit loads.
    f8 A  = ldg256(x0 + base);            // (2h,   2w)
    f8 Bv = ldg256(x0 + base + 64);       // (2h,   2w+1)
    f8 Cv = ldg256(x0 + base + 16384);    // (2h+1, 2w)
    f8 D  = ldg256(x0 + base + 16448);    // (2h+1, 2w+1)
    f8 P  = ldg256(x1 + pidx);            // pooled

    f8 OA, OB, OC, OD, R, TA, TB, TC, TD;

    LANE(v0); LANE(v1); LANE(v2); LANE(v3);
    LANE(v4); LANE(v5); LANE(v6); LANE(v7);

    // out0 (x0 layout)
    stg256(out + base,          OA);
    stg256(out + base + 64,     OB);
    stg256(out + base + 16384,  OC);
    stg256(out + base + 16448,  OD);

    // repl (pooled layout)
    stg256(out + REPL_F + pidx, R);

    // out3 (x0 layout)
    stg256(out + OUT3_F + base,         TA);
    stg256(out + OUT3_F + base + 64,    TB);
    stg256(out + OUT3_F + base + 16384, TC);
    stg256(out + OUT3_F + base + 16448, TD);
}

extern "C" void kernel_launch(void* const* d_in, const int* in_sizes, int n_in,
                              void* d_out, int out_size)
{
    (void)in_sizes; (void)n_in; (void)out_size;
    const float* x0 = (const float*)d_in[0];
    const float* x1 = (const float*)d_in[1];
    float* out = (float*)d_out;

    unpool_ls_kernel<<<NTHREADS / BLOCK, BLOCK>>>(x0, x1, out);
}